// round 7
// baseline (speedup 1.0000x reference)
#include <cuda_runtime.h>

#define INDIM   256
#define OUTDIM  256
#define BATCH   128
#define NK      12                  // dense slots per input: 11 coef + 1 residual
#define KS      16                  // k-splits over inputs
#define IPC     (INDIM / KS)        // 16 inputs per chunk
#define KCH     (IPC * NK)          // 192 dense k per chunk
#define OT      32                  // output cols per block
#define VSTR    33                  // padded s_V row stride (conflict-free)
#define NTHR    128

#define SMEM_V  (KCH * VSTR)                    // 6336 floats
#define SMEM_W  (KCH * BATCH)                   // 24576 floats
#define DYN_SMEM ((SMEM_V + SMEM_W) * 4)        // 123648 bytes

__device__ float g_part[KS * BATCH * OUTDIM];   // 2 MB split-K partials

// ---- per-x 12-slot dense basis row ------------------------------------------
__device__ __forceinline__ void basis12(float xv, const float* __restrict__ s_g,
                                        float* __restrict__ w)
{
    int j = 0;
    #pragma unroll
    for (int q = 1; q <= 13; ++q) j += (xv >= s_g[q]) ? 1 : 0;
    j = max(min(j, 10), 3);

    float lft[4], rgt[4];
    #pragma unroll
    for (int q = 1; q <= 3; ++q) { lft[q] = xv - s_g[j + 1 - q]; rgt[q] = s_g[j + q] - xv; }

    float N[4];
    N[0] = 1.0f;
    #pragma unroll
    for (int p = 1; p <= 3; ++p) {
        float saved = 0.0f;
        #pragma unroll
        for (int r = 0; r < p; ++r) {
            float temp = N[r] / (rgt[r + 1] + lft[p - r]);
            N[r] = saved + rgt[r + 1] * temp;
            saved = lft[p - r] * temp;
        }
        N[p] = saved;
    }
    const int idx = j - 3;                       // 0..7

    #pragma unroll
    for (int k = 0; k < 11; ++k) {
        float v = 0.0f;
        #pragma unroll
        for (int r = 0; r < 4; ++r)
            if (k - r == idx) v = N[r];          // predicated selects
        w[k] = v;
    }
    w[11] = xv / (1.0f + __expf(-xv));           // silu
}

// ---- Kernel 1: fused fold + basis + split-K GEMM ----------------------------
__global__ __launch_bounds__(NTHR)
void kan_gemm(const float* __restrict__ x,
              const float* __restrict__ grid,
              const float* __restrict__ coef,
              const float* __restrict__ rw,
              const float* __restrict__ uw)
{
    extern __shared__ __align__(16) float dyn[];
    float* s_V = dyn;                // [k][o_l] stride VSTR
    float* s_W = dyn + SMEM_V;       // [k][b]   stride 128

    __shared__ float s_g[16];
    __shared__ float s_u[OT * IPC];  // uw tile [o_l*16 + i_l]

    const int o0 = blockIdx.x * OT;
    const int ks = blockIdx.y;
    const int i0 = ks * IPC;
    const int t  = threadIdx.x;

    if (t < 15) s_g[t] = grid[t];

    // stage uw tile and drop rw straight into s_V slot 11
    #pragma unroll
    for (int q = t; q < OT * IPC; q += NTHR) {
        const int o_l = q >> 4, i_l = q & 15;
        const int gi = (o0 + o_l) * INDIM + i0 + i_l;
        s_u[q] = uw[gi];
        s_V[(i_l * NK + 11) * VSTR + o_l] = rw[gi];
    }
    __syncthreads();

    // fold coef * uw -> s_V (global reads coalesced; smem stores conflict-free)
    #pragma unroll
    for (int idx = t; idx < OT * IPC * 11; idx += NTHR) {
        const int o_l = idx / 176;               // 176 = 16 i * 11 k
        const int rem = idx - o_l * 176;
        const int i_l = rem / 11;
        const int kk  = rem - i_l * 11;
        const float c = coef[(size_t)(o0 + o_l) * (INDIM * 11) + (i0 + i_l) * 11 + kk];
        s_V[(i_l * NK + kk) * VSTR + o_l] = s_u[o_l * IPC + i_l] * c;
    }

    // basis: thread t = batch row b; 4x LDG.128 then 16 inline de Boor evals
    {
        const int b = t;
        const float4* xp = (const float4*)(x + b * INDIM + i0);   // 64B-aligned
        float4 xv4[4];
        #pragma unroll
        for (int c = 0; c < 4; ++c) xv4[c] = xp[c];

        float w[NK];
        #pragma unroll
        for (int c = 0; c < 4; ++c) {
            #pragma unroll
            for (int s = 0; s < 4; ++s) {
                const float xv = (s == 0) ? xv4[c].x : (s == 1) ? xv4[c].y
                               : (s == 2) ? xv4[c].z : xv4[c].w;
                basis12(xv, s_g, w);
                const int i_l = c * 4 + s;
                #pragma unroll
                for (int k = 0; k < NK; ++k)
                    s_W[(i_l * NK + k) * BATCH + b] = w[k];   // stride-1 in b
            }
        }
    }
    __syncthreads();

    // main loop: thread = (o_l, bg); 32 b-rows as 16 packed f32x2 accumulators
    const int o_l = t & 31;
    const int bg  = t >> 5;                      // 0..3, constant per warp
    const int bb  = bg * 32;

    unsigned long long acc2[16];
    #pragma unroll
    for (int j = 0; j < 16; ++j) acc2[j] = 0ull;

    #pragma unroll 4
    for (int k = 0; k < KCH; ++k) {
        const float v = s_V[k * VSTR + o_l];             // conflict-free LDS.32
        unsigned long long v2;
        asm("mov.b64 %0, {%1, %1};" : "=l"(v2) : "r"(__float_as_uint(v)));
        const ulonglong2* wp = (const ulonglong2*)&s_W[k * BATCH + bb];  // uniform -> broadcast
        #pragma unroll
        for (int j = 0; j < 8; ++j) {
            ulonglong2 w2 = wp[j];                        // LDS.128 broadcast
            asm("fma.rn.f32x2 %0, %1, %2, %0;" : "+l"(acc2[2*j])   : "l"(w2.x), "l"(v2));
            asm("fma.rn.f32x2 %0, %1, %2, %0;" : "+l"(acc2[2*j+1]) : "l"(w2.y), "l"(v2));
        }
    }

    float* pp = g_part + ((size_t)ks * BATCH + bb) * OUTDIM + o0 + o_l;
    #pragma unroll
    for (int j = 0; j < 16; ++j) {
        unsigned int lo, hi;
        asm("mov.b64 {%0, %1}, %2;" : "=r"(lo), "=r"(hi) : "l"(acc2[j]));
        pp[(2 * j)     * OUTDIM] = __uint_as_float(lo);   // coalesced over o_l
        pp[(2 * j + 1) * OUTDIM] = __uint_as_float(hi);
    }
}

// ---- Kernel 2: reduce split-K partials (float4, MLP=16) ---------------------
__global__ __launch_bounds__(128)
void kan_reduce(float4* __restrict__ out)
{
    const int idx = blockIdx.x * 128 + threadIdx.x;   // 8192 float4 tasks
    const float4* p = (const float4*)g_part;
    float4 s = make_float4(0.f, 0.f, 0.f, 0.f);
    #pragma unroll
    for (int z = 0; z < KS; ++z) {
        float4 v = p[(size_t)z * (BATCH * OUTDIM / 4) + idx];
        s.x += v.x; s.y += v.y; s.z += v.z; s.w += v.w;
    }
    out[idx] = s;
}

// ------------------------------------------------------------------------------
extern "C" void kernel_launch(void* const* d_in, const int* in_sizes, int n_in,
                              void* d_out, int out_size)
{
    const float* x    = (const float*)d_in[0];
    const float* grid = (const float*)d_in[1];
    const float* coef = (const float*)d_in[2];
    const float* rw   = (const float*)d_in[3];
    const float* uw   = (const float*)d_in[4];

    cudaFuncSetAttribute(kan_gemm, cudaFuncAttributeMaxDynamicSharedMemorySize, DYN_SMEM);

    kan_gemm  <<<dim3(OUTDIM / OT, KS), NTHR, DYN_SMEM>>>(x, grid, coef, rw, uw);
    kan_reduce<<<(BATCH * OUTDIM / 4) / 128, 128>>>((float4*)d_out);
}

// round 8
// speedup vs baseline: 1.3613x; 1.3613x over previous
#include <cuda_runtime.h>

#define INDIM   256
#define OUTDIM  256
#define BATCH   128
#define NK      12                  // dense slots per input: 11 coef + 1 residual
#define KS      16                  // k-splits over inputs
#define IPC     (INDIM / KS)        // 16 inputs per chunk
#define KCH     (IPC * NK)          // 192 dense k per chunk
#define OT      32                  // output cols per block
#define TBB     64                  // batch rows per block
#define VSTR    33                  // padded s_V row stride (conflict-free)
#define NTHR    256

#define SMEM_V  (KCH * VSTR)                    // 6336 floats (25.3 KB)
#define SMEM_W  (KCH * TBB)                     // 12288 floats (49.2 KB)
#define DYN_SMEM ((SMEM_V + SMEM_W) * 4)        // 74496 bytes -> 2 blocks/SM

__device__ float g_part[KS * BATCH * OUTDIM];   // 2 MB split-K partials

// ---- per-x 12-slot dense basis row ------------------------------------------
__device__ __forceinline__ void basis12(float xv, const float* __restrict__ s_g,
                                        float* __restrict__ w)
{
    int j = 0;
    #pragma unroll
    for (int q = 1; q <= 13; ++q) j += (xv >= s_g[q]) ? 1 : 0;
    j = max(min(j, 10), 3);

    float lft[4], rgt[4];
    #pragma unroll
    for (int q = 1; q <= 3; ++q) { lft[q] = xv - s_g[j + 1 - q]; rgt[q] = s_g[j + q] - xv; }

    float N[4];
    N[0] = 1.0f;
    #pragma unroll
    for (int p = 1; p <= 3; ++p) {
        float saved = 0.0f;
        #pragma unroll
        for (int r = 0; r < p; ++r) {
            float temp = N[r] / (rgt[r + 1] + lft[p - r]);
            N[r] = saved + rgt[r + 1] * temp;
            saved = lft[p - r] * temp;
        }
        N[p] = saved;
    }
    const int idx = j - 3;                       // 0..7

    #pragma unroll
    for (int k = 0; k < 11; ++k) {
        float v = 0.0f;
        #pragma unroll
        for (int r = 0; r < 4; ++r)
            if (k - r == idx) v = N[r];          // predicated selects
        w[k] = v;
    }
    w[11] = xv / (1.0f + __expf(-xv));           // silu
}

// ---- Kernel 1: fused fold + basis + split-K GEMM ----------------------------
__global__ __launch_bounds__(NTHR)
void kan_gemm(const float* __restrict__ x,
              const float* __restrict__ grid,
              const float* __restrict__ coef,
              const float* __restrict__ rw,
              const float* __restrict__ uw)
{
    extern __shared__ __align__(16) float dyn[];
    float* s_V = dyn;                // [k][o_l] stride VSTR
    float* s_W = dyn + SMEM_V;       // [k][b_l] stride TBB

    __shared__ float s_g[16];
    __shared__ float s_u[OT * IPC];  // uw tile [o_l*16 + i_l]

    const int o0 = blockIdx.x * OT;
    const int b0 = blockIdx.y * TBB;
    const int ks = blockIdx.z;
    const int i0 = ks * IPC;
    const int t  = threadIdx.x;

    if (t < 15) s_g[t] = grid[t];

    // stage uw tile; rw goes straight into s_V slot 11
    #pragma unroll
    for (int q = t; q < OT * IPC; q += NTHR) {
        const int o_l = q >> 4, i_l = q & 15;
        const int gi = (o0 + o_l) * INDIM + i0 + i_l;
        s_u[q] = uw[gi];
        s_V[(i_l * NK + 11) * VSTR + o_l] = rw[gi];
    }
    __syncthreads();

    // fold coef * uw -> s_V (coalesced global reads; conflict-free smem stores)
    #pragma unroll
    for (int idx = t; idx < OT * IPC * 11; idx += NTHR) {
        const int o_l = idx / 176;               // 176 = 16 i * 11 k
        const int rem = idx - o_l * 176;
        const int i_l = rem / 11;
        const int kk  = rem - i_l * 11;
        const float c = coef[(size_t)(o0 + o_l) * (INDIM * 11) + (i0 + i_l) * 11 + kk];
        s_V[(i_l * NK + kk) * VSTR + o_l] = s_u[o_l * IPC + i_l] * c;
    }

    // basis: thread = (b_l = t&63, 4-input group = t>>6); 1x LDG.128 + 4 evals
    {
        const int b_l  = t & 63;
        const int part = t >> 6;                 // 0..3
        const float4 xv4 = *(const float4*)(x + (b0 + b_l) * INDIM + i0 + part * 4);

        float w[NK];
        #pragma unroll
        for (int s = 0; s < 4; ++s) {
            const float xv = (s == 0) ? xv4.x : (s == 1) ? xv4.y
                           : (s == 2) ? xv4.z : xv4.w;
            basis12(xv, s_g, w);
            const int i_l = part * 4 + s;
            #pragma unroll
            for (int k = 0; k < NK; ++k)
                s_W[(i_l * NK + k) * TBB + b_l] = w[k];   // stride-1 in b_l
        }
    }
    __syncthreads();

    // main loop: thread = (o_l, bg); 8 b-rows as 4 packed f32x2 accumulators
    const int o_l = t & 31;
    const int bg  = t >> 5;                      // 0..7, constant per warp
    const int bb  = bg * 8;

    unsigned long long acc2[4] = {0ull, 0ull, 0ull, 0ull};

    #pragma unroll 4
    for (int k = 0; k < KCH; ++k) {
        const float v = s_V[k * VSTR + o_l];             // conflict-free LDS.32
        unsigned long long v2;
        asm("mov.b64 %0, {%1, %1};" : "=l"(v2) : "r"(__float_as_uint(v)));
        const ulonglong2* wp = (const ulonglong2*)&s_W[k * TBB + bb];  // 32B-aligned, uniform
        ulonglong2 w01 = wp[0];                          // LDS.128 broadcast
        ulonglong2 w23 = wp[1];
        asm("fma.rn.f32x2 %0, %1, %2, %0;" : "+l"(acc2[0]) : "l"(w01.x), "l"(v2));
        asm("fma.rn.f32x2 %0, %1, %2, %0;" : "+l"(acc2[1]) : "l"(w01.y), "l"(v2));
        asm("fma.rn.f32x2 %0, %1, %2, %0;" : "+l"(acc2[2]) : "l"(w23.x), "l"(v2));
        asm("fma.rn.f32x2 %0, %1, %2, %0;" : "+l"(acc2[3]) : "l"(w23.y), "l"(v2));
    }

    float* pp = g_part + ((size_t)ks * BATCH + b0 + bb) * OUTDIM + o0 + o_l;
    #pragma unroll
    for (int j = 0; j < 4; ++j) {
        unsigned int lo, hi;
        asm("mov.b64 {%0, %1}, %2;" : "=r"(lo), "=r"(hi) : "l"(acc2[j]));
        pp[(2 * j)     * OUTDIM] = __uint_as_float(lo);   // coalesced over o_l
        pp[(2 * j + 1) * OUTDIM] = __uint_as_float(hi);
    }
}

// ---- Kernel 2: reduce split-K partials (1 float/thread, 512 warps) ----------
__global__ __launch_bounds__(256)
void kan_reduce(float* __restrict__ out)
{
    const int idx = blockIdx.x * 256 + threadIdx.x;   // 32768 outputs
    float s = 0.0f;
    #pragma unroll
    for (int z = 0; z < KS; ++z)
        s += g_part[(size_t)z * (BATCH * OUTDIM) + idx];   // coalesced, MLP=16
    out[idx] = s;
}

// ------------------------------------------------------------------------------
extern "C" void kernel_launch(void* const* d_in, const int* in_sizes, int n_in,
                              void* d_out, int out_size)
{
    const float* x    = (const float*)d_in[0];
    const float* grid = (const float*)d_in[1];
    const float* coef = (const float*)d_in[2];
    const float* rw   = (const float*)d_in[3];
    const float* uw   = (const float*)d_in[4];

    cudaFuncSetAttribute(kan_gemm, cudaFuncAttributeMaxDynamicSharedMemorySize, DYN_SMEM);

    kan_gemm  <<<dim3(OUTDIM / OT, BATCH / TBB, KS), NTHR, DYN_SMEM>>>(x, grid, coef, rw, uw);
    kan_reduce<<<(BATCH * OUTDIM) / 256, 256>>>((float*)d_out);
}